// round 15
// baseline (speedup 1.0000x reference)
#include <cuda_runtime.h>
#include <cuda_bf16.h>

// PointPillarsScatter gather v14 (v12 skeleton, 8 cells/thread in two passes):
//  - d_cellinfo[cell] = (n<<24) | sum(pid); n==1 pid embedded (94.5% of occupied)
//  - v12 grid mapping kept (block = one channel group, consecutive cell groups ->
//    contiguous per-plane store regions; this is what DRAM efficiency wants, per R14)
//  - thread covers 8 consecutive cells as TWO sequential 4-cell passes sharing a[4]
//    registers: cellinfo = one 32B sector per 8 cells, warp stores 1KB contiguous
//    per channel plane (2x v12 burst size) -> higher DRAM write efficiency
//  - __launch_bounds__(256, 8) keeps 32-reg / 64-warp ceiling
//
// Inputs:
//   d_in[0]: pillar_feats  float32 [B=4, P=30000, C=64]
//   d_in[1]: pillar_coords int32   [B=4, P=30000, 2]  (y, x)
// Output: float32 [4, 64, 512, 512]

#define BEV_H 512
#define BEV_W 512
#define HW (BEV_H * BEV_W)       // 262144 = 2^18
#define C_DIM 64
#define P_DIM 30000
#define B_DIM 4
#define CAP 8
#define NOCT ((B_DIM * HW) / 8)  // 131072 octets of 8 cells

__device__ unsigned int   d_cellinfo[B_DIM * HW];     // 4 MB: (count<<24) | sum(pid)
__device__ unsigned short d_list[B_DIM * HW * CAP];   // 16 MB side lists (n>=2 only)

__global__ void pp_build_kernel(const int* __restrict__ coords) {
    int t = blockIdx.x * blockDim.x + threadIdx.x;
    if (t >= (B_DIM * P_DIM) / 2) return;

    int4 cc = reinterpret_cast<const int4*>(coords)[t];   // {y0,x0,y1,x1}
    int p0 = 2 * t, p1 = 2 * t + 1;

    int y0 = min(max(cc.x, 0), BEV_H - 1);
    int x0 = min(max(cc.y, 0), BEV_W - 1);
    int y1 = min(max(cc.z, 0), BEV_H - 1);
    int x1 = min(max(cc.w, 0), BEV_W - 1);

    int b0 = p0 / P_DIM, b1 = p1 / P_DIM;
    int pid0 = p0 - b0 * P_DIM, pid1 = p1 - b1 * P_DIM;
    int idx0 = b0 * HW + y0 * BEV_W + x0;
    int idx1 = b1 * HW + y1 * BEV_W + x1;

    unsigned old0 = atomicAdd(&d_cellinfo[idx0], (1u << 24) | (unsigned)pid0);
    unsigned old1 = atomicAdd(&d_cellinfo[idx1], (1u << 24) | (unsigned)pid1);
    unsigned pos0 = old0 >> 24, pos1 = old1 >> 24;
    if (pos0 < CAP) d_list[(size_t)idx0 * CAP + pos0] = (unsigned short)pid0;
    if (pos1 < CAP) d_list[(size_t)idx1 * CAP + pos1] = (unsigned short)pid1;
}

__global__ __launch_bounds__(256, 8) void pp_gather_kernel(const float* __restrict__ feats,
                                                           float* __restrict__ out) {
    int tid = blockIdx.x * blockDim.x + threadIdx.x;  // 0 .. 16*NOCT
    int oct = tid & (NOCT - 1);     // 8-cell octet (consecutive across warp)
    int chg = tid >> 17;            // channel group 0..15 (4 channels each)

    int idx0  = oct << 3;           // first cell index (b*HW + cell)
    int b     = idx0 >> 18;
    int cell0 = idx0 & (HW - 1);

    // 32B of cellinfo (8 cells): two uint4 loads, same sector -> one round trip
    const uint4* info = reinterpret_cast<const uint4*>(&d_cellinfo[idx0]);
    uint4 wv0 = info[0];
    uint4 wv1 = info[1];

    const float* fb = feats + (size_t)b * P_DIM * C_DIM + (chg << 2);
    float* o = out + ((size_t)b * C_DIM + (size_t)(chg << 2)) * HW + cell0;

    #pragma unroll
    for (int pass = 0; pass < 2; pass++) {
        unsigned w[4];
        if (pass == 0) { w[0] = wv0.x; w[1] = wv0.y; w[2] = wv0.z; w[3] = wv0.w; }
        else           { w[0] = wv1.x; w[1] = wv1.y; w[2] = wv1.z; w[3] = wv1.w; }

        // Hot path: predicated n==1 load directly into the store registers.
        float4 a[4];
        #pragma unroll
        for (int ci = 0; ci < 4; ci++) {
            float4 v = make_float4(0.f, 0.f, 0.f, 0.f);
            if ((w[ci] >> 24) == 1) {
                unsigned pid = w[ci] & 0xFFFFFFu;
                v = *reinterpret_cast<const float4*>(fb + (size_t)pid * C_DIM);
            }
            a[ci] = v;
        }

        // Rare path (0.65% of cells): inline multi-pillar sum from the side list.
        if (((w[0] | w[1] | w[2] | w[3]) >> 24) > 1) {
            #pragma unroll
            for (int ci = 0; ci < 4; ci++) {
                int n = (int)(w[ci] >> 24);
                if (n < 2) continue;
                n = min(n, CAP);
                float4 s = make_float4(0.f, 0.f, 0.f, 0.f);
                const unsigned short* lst = &d_list[(size_t)(idx0 + pass * 4 + ci) * CAP];
                for (int i = 0; i < n; i++) {
                    float4 v = *reinterpret_cast<const float4*>(fb + (size_t)lst[i] * C_DIM);
                    s.x += v.x; s.y += v.y; s.z += v.z; s.w += v.w;
                }
                a[ci] = s;
            }
        }

        float* op = o + pass * 4;   // pass 1 fills the adjacent 16B per plane
        __stcs(reinterpret_cast<float4*>(op + 0 * (size_t)HW), make_float4(a[0].x, a[1].x, a[2].x, a[3].x));
        __stcs(reinterpret_cast<float4*>(op + 1 * (size_t)HW), make_float4(a[0].y, a[1].y, a[2].y, a[3].y));
        __stcs(reinterpret_cast<float4*>(op + 2 * (size_t)HW), make_float4(a[0].z, a[1].z, a[2].z, a[3].z));
        __stcs(reinterpret_cast<float4*>(op + 3 * (size_t)HW), make_float4(a[0].w, a[1].w, a[2].w, a[3].w));
    }
}

extern "C" void kernel_launch(void* const* d_in, const int* in_sizes, int n_in,
                              void* d_out, int out_size) {
    const float* feats  = (const float*)d_in[0];
    const int*   coords = (const int*)d_in[1];
    float*       out    = (float*)d_out;

    // Zero the fused cell words (4 MB, graph-capturable)
    void* info_ptr = nullptr;
    cudaGetSymbolAddress(&info_ptr, d_cellinfo);
    cudaMemsetAsync(info_ptr, 0, (size_t)B_DIM * HW * sizeof(unsigned int));

    int n_pairs = (B_DIM * P_DIM) / 2;             // 60,000 threads, 2 pillars each
    pp_build_kernel<<<(n_pairs + 255) / 256, 256>>>(coords);

    int n_threads = 16 * NOCT;                     // 2,097,152
    pp_gather_kernel<<<n_threads / 256, 256>>>(feats, out);
}

// round 16
// speedup vs baseline: 1.9466x; 1.9466x over previous
#include <cuda_runtime.h>
#include <cuda_bf16.h>

// PointPillarsScatter gather v15 (v12 + two dense 4-cell spans per thread):
//  - store-density law (R12/R14/R15): every warp store instruction must be fully
//    dense -> 4 consecutive cells x 16B per thread, exactly v12's store shape.
//  - each thread handles TWO disjoint spans (same cells, batches b and b+2):
//    both cellinfo uint4 loads issue back-to-back (MLP 2, one latency event)
//    -> mandatory-latency events per cell halved vs v12.
//  - __launch_bounds__(256, 6) caps regs at 42 -> 48 warps/SM (= v12 achieved occ)
//
// Inputs:
//   d_in[0]: pillar_feats  float32 [B=4, P=30000, C=64]
//   d_in[1]: pillar_coords int32   [B=4, P=30000, 2]  (y, x)
// Output: float32 [4, 64, 512, 512]

#define BEV_H 512
#define BEV_W 512
#define HW (BEV_H * BEV_W)      // 262144 = 2^18
#define C_DIM 64
#define P_DIM 30000
#define B_DIM 4
#define CAP 8
#define NGRP ((B_DIM * HW) / 4) // 262144 groups of 4 cells
#define HGRP (NGRP / 2)         // 131072: half the groups (batches 0-1)

__device__ unsigned int   d_cellinfo[B_DIM * HW];     // 4 MB: (count<<24) | sum(pid)
__device__ unsigned short d_list[B_DIM * HW * CAP];   // 16 MB side lists (n>=2 only)

__global__ void pp_build_kernel(const int* __restrict__ coords) {
    int t = blockIdx.x * blockDim.x + threadIdx.x;
    if (t >= (B_DIM * P_DIM) / 2) return;

    int4 cc = reinterpret_cast<const int4*>(coords)[t];   // {y0,x0,y1,x1}
    int p0 = 2 * t, p1 = 2 * t + 1;

    int y0 = min(max(cc.x, 0), BEV_H - 1);
    int x0 = min(max(cc.y, 0), BEV_W - 1);
    int y1 = min(max(cc.z, 0), BEV_H - 1);
    int x1 = min(max(cc.w, 0), BEV_W - 1);

    int b0 = p0 / P_DIM, b1 = p1 / P_DIM;
    int pid0 = p0 - b0 * P_DIM, pid1 = p1 - b1 * P_DIM;
    int idx0 = b0 * HW + y0 * BEV_W + x0;
    int idx1 = b1 * HW + y1 * BEV_W + x1;

    unsigned old0 = atomicAdd(&d_cellinfo[idx0], (1u << 24) | (unsigned)pid0);
    unsigned old1 = atomicAdd(&d_cellinfo[idx1], (1u << 24) | (unsigned)pid1);
    unsigned pos0 = old0 >> 24, pos1 = old1 >> 24;
    if (pos0 < CAP) d_list[(size_t)idx0 * CAP + pos0] = (unsigned short)pid0;
    if (pos1 < CAP) d_list[(size_t)idx1 * CAP + pos1] = (unsigned short)pid1;
}

// Process one dense 4-cell span: predicated n==1 loads + rare side-list, 4 dense stores.
__device__ __forceinline__ void span_process(unsigned wx, unsigned wy, unsigned wz, unsigned ww,
                                             int idx0, const float* __restrict__ fb,
                                             float* __restrict__ o) {
    unsigned w[4] = {wx, wy, wz, ww};

    float4 a[4];
    #pragma unroll
    for (int ci = 0; ci < 4; ci++) {
        float4 v = make_float4(0.f, 0.f, 0.f, 0.f);
        if ((w[ci] >> 24) == 1) {
            unsigned pid = w[ci] & 0xFFFFFFu;
            v = *reinterpret_cast<const float4*>(fb + (size_t)pid * C_DIM);
        }
        a[ci] = v;
    }

    if (((w[0] | w[1] | w[2] | w[3]) >> 24) > 1) {     // rare: 0.65% of cells
        #pragma unroll
        for (int ci = 0; ci < 4; ci++) {
            int n = (int)(w[ci] >> 24);
            if (n < 2) continue;
            n = min(n, CAP);
            float4 s = make_float4(0.f, 0.f, 0.f, 0.f);
            const unsigned short* lst = &d_list[(size_t)(idx0 + ci) * CAP];
            for (int i = 0; i < n; i++) {
                float4 v = *reinterpret_cast<const float4*>(fb + (size_t)lst[i] * C_DIM);
                s.x += v.x; s.y += v.y; s.z += v.z; s.w += v.w;
            }
            a[ci] = s;
        }
    }

    __stcs(reinterpret_cast<float4*>(o + 0 * (size_t)HW), make_float4(a[0].x, a[1].x, a[2].x, a[3].x));
    __stcs(reinterpret_cast<float4*>(o + 1 * (size_t)HW), make_float4(a[0].y, a[1].y, a[2].y, a[3].y));
    __stcs(reinterpret_cast<float4*>(o + 2 * (size_t)HW), make_float4(a[0].z, a[1].z, a[2].z, a[3].z));
    __stcs(reinterpret_cast<float4*>(o + 3 * (size_t)HW), make_float4(a[0].w, a[1].w, a[2].w, a[3].w));
}

__global__ __launch_bounds__(256, 6) void pp_gather_kernel(const float* __restrict__ feats,
                                                           float* __restrict__ out) {
    int tid = blockIdx.x * blockDim.x + threadIdx.x;  // 0 .. 16*HGRP
    int grp = tid & (HGRP - 1);     // span A group, batches 0-1 (consecutive across warp)
    int chg = tid >> 17;            // channel group 0..15 (4 channels each)

    int idxA  = grp << 2;           // span A first cell (b in {0,1})
    int idxB  = idxA + 2 * HW;      // span B: same cell coords, batch b+2
    int bA    = idxA >> 18;
    int cell0 = idxA & (HW - 1);

    // Both cellinfo loads issue back-to-back: one latency event for 8 cells.
    uint4 wA = *reinterpret_cast<const uint4*>(&d_cellinfo[idxA]);
    uint4 wB = *reinterpret_cast<const uint4*>(&d_cellinfo[idxB]);

    const float* fbA = feats + (size_t)bA * P_DIM * C_DIM + (chg << 2);
    const float* fbB = fbA + (size_t)2 * P_DIM * C_DIM;
    float* oA = out + ((size_t)bA * C_DIM + (size_t)(chg << 2)) * HW + cell0;
    float* oB = oA + (size_t)2 * C_DIM * HW;

    span_process(wA.x, wA.y, wA.z, wA.w, idxA, fbA, oA);
    span_process(wB.x, wB.y, wB.z, wB.w, idxB, fbB, oB);
}

extern "C" void kernel_launch(void* const* d_in, const int* in_sizes, int n_in,
                              void* d_out, int out_size) {
    const float* feats  = (const float*)d_in[0];
    const int*   coords = (const int*)d_in[1];
    float*       out    = (float*)d_out;

    // Zero the fused cell words (4 MB, graph-capturable)
    void* info_ptr = nullptr;
    cudaGetSymbolAddress(&info_ptr, d_cellinfo);
    cudaMemsetAsync(info_ptr, 0, (size_t)B_DIM * HW * sizeof(unsigned int));

    int n_pairs = (B_DIM * P_DIM) / 2;             // 60,000 threads, 2 pillars each
    pp_build_kernel<<<(n_pairs + 255) / 256, 256>>>(coords);

    int n_threads = 16 * HGRP;                     // 2,097,152
    pp_gather_kernel<<<n_threads / 256, 256>>>(feats, out);
}

// round 17
// speedup vs baseline: 1.9969x; 1.0258x over previous
#include <cuda_runtime.h>
#include <cuda_bf16.h>

// PointPillarsScatter gather v16 (v12 + 2-channel-group blocks sharing cellinfo):
//  - d_cellinfo[cell] = (n<<24) | sum(pid); n==1 pid embedded (94.5% of occupied)
//  - block = 512 threads = 2 channel groups x 256 consecutive cell groups:
//    per-plane store runs stay 4KB (v12's DRAM-efficient shape) while the two
//    halves read the SAME 4KB of cellinfo -> L1 hit for the second half,
//    halving the 64MB of redundant cellinfo L2 traffic.
//  - hot path: predicated n==1 float4 load into store regs; n>=2 inline rare block
//  - __launch_bounds__(512, 4) caps regs at 32 -> 64-warp ceiling
//
// Inputs:
//   d_in[0]: pillar_feats  float32 [B=4, P=30000, C=64]
//   d_in[1]: pillar_coords int32   [B=4, P=30000, 2]  (y, x)
// Output: float32 [4, 64, 512, 512]

#define BEV_H 512
#define BEV_W 512
#define HW (BEV_H * BEV_W)      // 262144 = 2^18
#define C_DIM 64
#define P_DIM 30000
#define B_DIM 4
#define CAP 8
#define NGRP ((B_DIM * HW) / 4) // 262144 groups of 4 cells
#define TILES (NGRP / 256)      // 1024 tiles of 256 groups

__device__ unsigned int   d_cellinfo[B_DIM * HW];     // 4 MB: (count<<24) | sum(pid)
__device__ unsigned short d_list[B_DIM * HW * CAP];   // 16 MB side lists (n>=2 only)

__global__ void pp_build_kernel(const int* __restrict__ coords) {
    int t = blockIdx.x * blockDim.x + threadIdx.x;
    if (t >= (B_DIM * P_DIM) / 2) return;

    int4 cc = reinterpret_cast<const int4*>(coords)[t];   // {y0,x0,y1,x1}
    int p0 = 2 * t, p1 = 2 * t + 1;

    int y0 = min(max(cc.x, 0), BEV_H - 1);
    int x0 = min(max(cc.y, 0), BEV_W - 1);
    int y1 = min(max(cc.z, 0), BEV_H - 1);
    int x1 = min(max(cc.w, 0), BEV_W - 1);

    int b0 = p0 / P_DIM, b1 = p1 / P_DIM;
    int pid0 = p0 - b0 * P_DIM, pid1 = p1 - b1 * P_DIM;
    int idx0 = b0 * HW + y0 * BEV_W + x0;
    int idx1 = b1 * HW + y1 * BEV_W + x1;

    unsigned old0 = atomicAdd(&d_cellinfo[idx0], (1u << 24) | (unsigned)pid0);
    unsigned old1 = atomicAdd(&d_cellinfo[idx1], (1u << 24) | (unsigned)pid1);
    unsigned pos0 = old0 >> 24, pos1 = old1 >> 24;
    if (pos0 < CAP) d_list[(size_t)idx0 * CAP + pos0] = (unsigned short)pid0;
    if (pos1 < CAP) d_list[(size_t)idx1 * CAP + pos1] = (unsigned short)pid1;
}

__global__ __launch_bounds__(512, 4) void pp_gather_kernel(const float* __restrict__ feats,
                                                           float* __restrict__ out) {
    // Block = 2 channel groups x 256 consecutive cell groups.
    int grp = ((blockIdx.x & (TILES - 1)) << 8) | (threadIdx.x & 255);
    int chg = ((blockIdx.x >> 10) << 1)         | (threadIdx.x >> 8);   // 0..15

    int idx0  = grp << 2;
    int b     = idx0 >> 18;
    int cell0 = idx0 & (HW - 1);

    // Both block halves read the same 16B word: half 2 hits L1.
    uint4 wv = *reinterpret_cast<const uint4*>(&d_cellinfo[idx0]);
    unsigned w[4] = {wv.x, wv.y, wv.z, wv.w};

    const float* fb = feats + (size_t)b * P_DIM * C_DIM + (chg << 2);

    // Hot path: predicated n==1 load directly into the store registers.
    float4 a[4];
    #pragma unroll
    for (int ci = 0; ci < 4; ci++) {
        float4 v = make_float4(0.f, 0.f, 0.f, 0.f);
        if ((w[ci] >> 24) == 1) {
            unsigned pid = w[ci] & 0xFFFFFFu;
            v = *reinterpret_cast<const float4*>(fb + (size_t)pid * C_DIM);
        }
        a[ci] = v;
    }

    // Rare path (0.65% of cells): inline multi-pillar sum from the side list.
    if (((w[0] | w[1] | w[2] | w[3]) >> 24) > 1) {
        #pragma unroll
        for (int ci = 0; ci < 4; ci++) {
            int n = (int)(w[ci] >> 24);
            if (n < 2) continue;
            n = min(n, CAP);
            float4 s = make_float4(0.f, 0.f, 0.f, 0.f);
            const unsigned short* lst = &d_list[(size_t)(idx0 + ci) * CAP];
            for (int i = 0; i < n; i++) {
                float4 v = *reinterpret_cast<const float4*>(fb + (size_t)lst[i] * C_DIM);
                s.x += v.x; s.y += v.y; s.z += v.z; s.w += v.w;
            }
            a[ci] = s;
        }
    }

    float* o = out + ((size_t)b * C_DIM + (size_t)(chg << 2)) * HW + cell0;
    __stcs(reinterpret_cast<float4*>(o + 0 * (size_t)HW), make_float4(a[0].x, a[1].x, a[2].x, a[3].x));
    __stcs(reinterpret_cast<float4*>(o + 1 * (size_t)HW), make_float4(a[0].y, a[1].y, a[2].y, a[3].y));
    __stcs(reinterpret_cast<float4*>(o + 2 * (size_t)HW), make_float4(a[0].z, a[1].z, a[2].z, a[3].z));
    __stcs(reinterpret_cast<float4*>(o + 3 * (size_t)HW), make_float4(a[0].w, a[1].w, a[2].w, a[3].w));
}

extern "C" void kernel_launch(void* const* d_in, const int* in_sizes, int n_in,
                              void* d_out, int out_size) {
    const float* feats  = (const float*)d_in[0];
    const int*   coords = (const int*)d_in[1];
    float*       out    = (float*)d_out;

    // Zero the fused cell words (4 MB, graph-capturable)
    void* info_ptr = nullptr;
    cudaGetSymbolAddress(&info_ptr, d_cellinfo);
    cudaMemsetAsync(info_ptr, 0, (size_t)B_DIM * HW * sizeof(unsigned int));

    int n_pairs = (B_DIM * P_DIM) / 2;             // 60,000 threads, 2 pillars each
    pp_build_kernel<<<(n_pairs + 255) / 256, 256>>>(coords);

    pp_gather_kernel<<<8192, 512>>>(feats, out);   // 16*NGRP/512 threads
}